// round 12
// baseline (speedup 1.0000x reference)
#include <cuda_runtime.h>
#include <cuda_bf16.h>
#include <math.h>

#define BATCH    32
#define SRC_LEN  2048
#define DIM      1024
#define TOTAL_ROWS (SRC_LEN * BATCH)        // 65536
#define WARPS_PER_BLOCK 16
#define BLOCK_THREADS   (WARPS_PER_BLOCK * 32)   // 512

// e_dec[b] + bias, produced by score kernel blocks 0..31, consumed by softmax.
__device__ float g_edec[BATCH];

// ---------------------------------------------------------------------------
// Kernel A (score): out[b, s] = enc_outputs[s,b,:] . w_enc       (RAW score)
// Measured-best per-warp shape: one row per warp, 8 independent LDG.128/lane
// (__ldcs). 512-thread blocks halve per-block fixed costs; 64KB contiguous
// span per block. regs capped for 4 CTAs/SM (64 warps/SM).
// ---------------------------------------------------------------------------
__global__ void __launch_bounds__(BLOCK_THREADS, 4)
score_kernel(const float* __restrict__ enc_outputs,
             const float* __restrict__ W,
             const float* __restrict__ dec_hidden,
             const float* __restrict__ bias,
             float* __restrict__ out)
{
#if __CUDA_ARCH__ >= 900
    cudaTriggerProgrammaticLaunchCompletion();
#endif

    __shared__ float4 s_wenc[DIM / 4];   // 4 KB
    __shared__ float  red[WARPS_PER_BLOCK];

    const int tid = threadIdx.x;
    const float4* we_g = reinterpret_cast<const float4*>(W + DIM);
    for (int i = tid; i < DIM / 4; i += BLOCK_THREADS)
        s_wenc[i] = we_g[i];
    __syncthreads();

    const int warp = tid >> 5;
    const int lane = tid & 31;
    const int flat = blockIdx.x * WARPS_PER_BLOCK + warp;   // = s*32 + b
    const int s = flat >> 5;
    const int b = flat & 31;

    const float4* row = reinterpret_cast<const float4*>(
        enc_outputs + (size_t)flat * DIM);

    float acc = 0.f;
#pragma unroll
    for (int i = 0; i < 8; ++i) {
        float4 v = __ldcs(&row[lane + i * 32]);   // evict-first stream
        float4 w = s_wenc[lane + i * 32];
        acc += v.x * w.x + v.y * w.y + v.z * w.z + v.w * w.w;
    }
#pragma unroll
    for (int o = 16; o > 0; o >>= 1)
        acc += __shfl_xor_sync(0xFFFFFFFFu, acc, o);

    if (lane == 0)
        out[(size_t)b * SRC_LEN + s] = acc;       // raw score

    // ---- blocks 0..31: g_edec[blockIdx] = dec . w_dec + bias (hidden) ----
    if (blockIdx.x < BATCH) {
        const int bb = blockIdx.x;
        // 512 threads x float2 covers 1024 floats
        const float2* dh = reinterpret_cast<const float2*>(dec_hidden + (size_t)bb * DIM);
        const float2* wd = reinterpret_cast<const float2*>(W);
        float2 a = dh[tid];
        float2 w = wd[tid];
        float ed = a.x * w.x + a.y * w.y;
#pragma unroll
        for (int o = 16; o > 0; o >>= 1)
            ed += __shfl_xor_sync(0xFFFFFFFFu, ed, o);
        if (lane == 0) red[warp] = ed;
        __syncthreads();
        if (tid == 0) {
            float t = 0.f;
#pragma unroll
            for (int i = 0; i < WARPS_PER_BLOCK; ++i) t += red[i];
            g_edec[bb] = t + bias[0];
        }
    }
}

// ---------------------------------------------------------------------------
// Kernel B (softmax): PDL-launched; parks at GridDependencySynchronize while
// kernel A streams. R7-measured-best shape: 1024 threads, float2 per thread.
// tanh in [-1,1] -> exp cannot overflow -> no max pass.
// ---------------------------------------------------------------------------
#define SM_THREADS 1024
#define SM_WARPS   (SM_THREADS / 32)        // 32

__global__ void __launch_bounds__(SM_THREADS)
softmax_kernel(float* __restrict__ out)
{
    __shared__ float red[SM_WARPS];

#if __CUDA_ARCH__ >= 900
    cudaGridDependencySynchronize();        // wait for score grid completion
#endif

    const int b    = blockIdx.x;
    const int tid  = threadIdx.x;
    const int lane = tid & 31;
    const int warp = tid >> 5;

    float* row = out + (size_t)b * SRC_LEN;

    float2 v;
    {
        const float2* rp = reinterpret_cast<const float2*>(row);
        v = __ldcg(&rp[tid]);                // L2-fresh producer data
    }
    const float edec_b = __ldcg(&g_edec[b]);

    v.x = __expf(tanhf(v.x + edec_b));
    v.y = __expf(tanhf(v.y + edec_b));
    float sum = v.x + v.y;
#pragma unroll
    for (int o = 16; o > 0; o >>= 1)
        sum += __shfl_xor_sync(0xFFFFFFFFu, sum, o);
    if (lane == 0) red[warp] = sum;
    __syncthreads();
    if (warp == 0) {
        float t = red[lane];
#pragma unroll
        for (int o = 16; o > 0; o >>= 1)
            t += __shfl_xor_sync(0xFFFFFFFFu, t, o);
        if (lane == 0) red[0] = t;
    }
    __syncthreads();
    const float inv = 1.0f / red[0];

    v.x *= inv;
    v.y *= inv;
    reinterpret_cast<float2*>(row)[tid] = v;
}

// ---------------------------------------------------------------------------
extern "C" void kernel_launch(void* const* d_in, const int* in_sizes, int n_in,
                              void* d_out, int out_size)
{
    const float* dec_hidden  = (const float*)d_in[0];   // (32, 1024)
    const float* enc_outputs = (const float*)d_in[1];   // (2048, 32, 1024)
    const float* W           = (const float*)d_in[2];   // (1, 2048)
    const float* bias        = (const float*)d_in[3];   // (1,)
    float* out = (float*)d_out;                          // (32, 2048)

    score_kernel<<<TOTAL_ROWS / WARPS_PER_BLOCK, BLOCK_THREADS>>>(
        enc_outputs, W, dec_hidden, bias, out);

    // Softmax with programmatic dependent launch: its launch/dispatch overlaps
    // the score kernel; data dependency enforced by GridDependencySync.
    cudaLaunchConfig_t cfg = {};
    cfg.gridDim  = dim3(BATCH, 1, 1);
    cfg.blockDim = dim3(SM_THREADS, 1, 1);
    cfg.dynamicSmemBytes = 0;
    cudaLaunchAttribute attrs[1];
    attrs[0].id = cudaLaunchAttributeProgrammaticStreamSerialization;
    attrs[0].val.programmaticStreamSerializationAllowed = 1;
    cfg.attrs = attrs;
    cfg.numAttrs = 1;
    cudaLaunchKernelEx(&cfg, softmax_kernel, out);
}

// round 13
// speedup vs baseline: 1.0035x; 1.0035x over previous
#include <cuda_runtime.h>
#include <cuda_bf16.h>
#include <math.h>

#define BATCH    32
#define SRC_LEN  2048
#define DIM      1024
#define TOTAL_ROWS (SRC_LEN * BATCH)        // 65536
#define WARPS_PER_BLOCK 8
#define BLOCK_THREADS   (WARPS_PER_BLOCK * 32)   // 256

// e_dec[b] + bias, produced by score kernel blocks 0..31, consumed by softmax.
__device__ float g_edec[BATCH];

// ---------------------------------------------------------------------------
// Kernel A (score): out[b, s] = enc_outputs[s,b,:] . w_enc       (RAW score)
// R11-measured-best: 256-thr blocks, one row per warp (contiguous 32KB/block),
// 8 independent LDG.128/lane (__ldcs), regs capped for 8 CTAs/SM.
// Triggers PDL completion at entry so the dependent softmax grid dispatches
// and parks while this kernel streams.
// ---------------------------------------------------------------------------
__global__ void __launch_bounds__(BLOCK_THREADS, 8)
score_kernel(const float* __restrict__ enc_outputs,
             const float* __restrict__ W,
             const float* __restrict__ dec_hidden,
             const float* __restrict__ bias,
             float* __restrict__ out)
{
#if __CUDA_ARCH__ >= 900
    cudaTriggerProgrammaticLaunchCompletion();
#endif

    __shared__ float4 s_wenc[DIM / 4];   // 4 KB
    __shared__ float  red[WARPS_PER_BLOCK];

    const int tid = threadIdx.x;
    const float4* we_g = reinterpret_cast<const float4*>(W + DIM);
    for (int i = tid; i < DIM / 4; i += BLOCK_THREADS)
        s_wenc[i] = we_g[i];
    __syncthreads();

    const int warp = tid >> 5;
    const int lane = tid & 31;
    const int flat = blockIdx.x * WARPS_PER_BLOCK + warp;   // = s*32 + b
    const int s = flat >> 5;
    const int b = flat & 31;

    const float4* row = reinterpret_cast<const float4*>(
        enc_outputs + (size_t)flat * DIM);

    float acc = 0.f;
#pragma unroll
    for (int i = 0; i < 8; ++i) {
        float4 v = __ldcs(&row[lane + i * 32]);   // evict-first stream
        float4 w = s_wenc[lane + i * 32];
        acc += v.x * w.x + v.y * w.y + v.z * w.z + v.w * w.w;
    }
#pragma unroll
    for (int o = 16; o > 0; o >>= 1)
        acc += __shfl_xor_sync(0xFFFFFFFFu, acc, o);

    if (lane == 0)
        out[(size_t)b * SRC_LEN + s] = acc;       // raw score

    // ---- blocks 0..31: g_edec[blockIdx] = dec . w_dec + bias (hidden) ----
    if (blockIdx.x < BATCH) {
        const int bb = blockIdx.x;
        const float4* dh = reinterpret_cast<const float4*>(dec_hidden + (size_t)bb * DIM);
        const float4* wd = reinterpret_cast<const float4*>(W);
        float4 a = dh[tid];
        float4 w = wd[tid];
        float ed = a.x * w.x + a.y * w.y + a.z * w.z + a.w * w.w;
#pragma unroll
        for (int o = 16; o > 0; o >>= 1)
            ed += __shfl_xor_sync(0xFFFFFFFFu, ed, o);
        if (lane == 0) red[warp] = ed;
        __syncthreads();
        if (tid == 0) {
            float t = 0.f;
#pragma unroll
            for (int i = 0; i < WARPS_PER_BLOCK; ++i) t += red[i];
            g_edec[bb] = t + bias[0];
        }
    }
}

// ---------------------------------------------------------------------------
// Kernel B (softmax): PDL-launched; parks at GridDependencySynchronize while
// kernel A streams. 512 threads x one float4 per thread (single LDG.128 /
// STG.128 per thread). tanh in [-1,1] -> exp cannot overflow -> no max pass.
// ---------------------------------------------------------------------------
#define SM_THREADS 512
#define SM_WARPS   (SM_THREADS / 32)        // 16

__global__ void __launch_bounds__(SM_THREADS)
softmax_kernel(float* __restrict__ out)
{
    __shared__ float red[SM_WARPS];

#if __CUDA_ARCH__ >= 900
    cudaGridDependencySynchronize();        // wait for score grid completion
#endif

    const int b    = blockIdx.x;
    const int tid  = threadIdx.x;
    const int lane = tid & 31;
    const int warp = tid >> 5;

    float4* row4 = reinterpret_cast<float4*>(out + (size_t)b * SRC_LEN);

    float4 v = __ldcg(&row4[tid]);          // one LDG.128: 4 row values
    const float edec_b = __ldcg(&g_edec[b]);

    v.x = __expf(tanhf(v.x + edec_b));
    v.y = __expf(tanhf(v.y + edec_b));
    v.z = __expf(tanhf(v.z + edec_b));
    v.w = __expf(tanhf(v.w + edec_b));
    float sum = (v.x + v.y) + (v.z + v.w);
#pragma unroll
    for (int o = 16; o > 0; o >>= 1)
        sum += __shfl_xor_sync(0xFFFFFFFFu, sum, o);
    if (lane == 0) red[warp] = sum;
    __syncthreads();
    if (warp == 0) {
        float t = (lane < SM_WARPS) ? red[lane] : 0.f;
#pragma unroll
        for (int o = 16; o > 0; o >>= 1)
            t += __shfl_xor_sync(0xFFFFFFFFu, t, o);
        if (lane == 0) red[0] = t;
    }
    __syncthreads();
    const float inv = 1.0f / red[0];

    v.x *= inv; v.y *= inv; v.z *= inv; v.w *= inv;
    row4[tid] = v;                           // one STG.128
}

// ---------------------------------------------------------------------------
extern "C" void kernel_launch(void* const* d_in, const int* in_sizes, int n_in,
                              void* d_out, int out_size)
{
    const float* dec_hidden  = (const float*)d_in[0];   // (32, 1024)
    const float* enc_outputs = (const float*)d_in[1];   // (2048, 32, 1024)
    const float* W           = (const float*)d_in[2];   // (1, 2048)
    const float* bias        = (const float*)d_in[3];   // (1,)
    float* out = (float*)d_out;                          // (32, 2048)

    score_kernel<<<TOTAL_ROWS / WARPS_PER_BLOCK, BLOCK_THREADS>>>(
        enc_outputs, W, dec_hidden, bias, out);

    // Softmax with programmatic dependent launch: its launch/dispatch overlaps
    // the score kernel; data dependency enforced by GridDependencySync.
    cudaLaunchConfig_t cfg = {};
    cfg.gridDim  = dim3(BATCH, 1, 1);
    cfg.blockDim = dim3(SM_THREADS, 1, 1);
    cfg.dynamicSmemBytes = 0;
    cudaLaunchAttribute attrs[1];
    attrs[0].id = cudaLaunchAttributeProgrammaticStreamSerialization;
    attrs[0].val.programmaticStreamSerializationAllowed = 1;
    cfg.attrs = attrs;
    cfg.numAttrs = 1;
    cudaLaunchKernelEx(&cfg, softmax_kernel, out);
}

// round 14
// speedup vs baseline: 1.0486x; 1.0449x over previous
#include <cuda_runtime.h>
#include <cuda_bf16.h>
#include <math.h>

#define BATCH    32
#define SRC_LEN  2048
#define DIM      1024
#define TOTAL_ROWS (SRC_LEN * BATCH)        // 65536
#define WARPS_PER_BLOCK 8
#define BLOCK_THREADS   (WARPS_PER_BLOCK * 32)

// e_dec[b] + bias, produced by score kernel blocks 0..31, consumed by softmax.
__device__ float g_edec[BATCH];

// ---------------------------------------------------------------------------
// Kernel A (score): out[b, s] = enc_outputs[s,b,:] . w_enc       (RAW score)
// R9-measured-best shape: flat grid, one row per warp (contiguous 32KB/block),
// 8 independent LDG.128/lane (__ldcs), regs capped for 8 CTAs/SM.
// Triggers programmatic launch completion at entry so the dependent softmax
// grid dispatches and parks while this kernel streams.
// ---------------------------------------------------------------------------
__global__ void __launch_bounds__(BLOCK_THREADS, 8)
score_kernel(const float* __restrict__ enc_outputs,
             const float* __restrict__ W,
             const float* __restrict__ dec_hidden,
             const float* __restrict__ bias,
             float* __restrict__ out)
{
#if __CUDA_ARCH__ >= 900
    cudaTriggerProgrammaticLaunchCompletion();
#endif

    __shared__ float4 s_wenc[DIM / 4];   // 4 KB
    __shared__ float  red[WARPS_PER_BLOCK];

    const int tid = threadIdx.x;
    const float4* we_g = reinterpret_cast<const float4*>(W + DIM);
    for (int i = tid; i < DIM / 4; i += BLOCK_THREADS)
        s_wenc[i] = we_g[i];
    __syncthreads();

    const int warp = tid >> 5;
    const int lane = tid & 31;
    const int flat = blockIdx.x * WARPS_PER_BLOCK + warp;   // = s*32 + b
    const int s = flat >> 5;
    const int b = flat & 31;

    const float4* row = reinterpret_cast<const float4*>(
        enc_outputs + (size_t)flat * DIM);

    float acc = 0.f;
#pragma unroll
    for (int i = 0; i < 8; ++i) {
        float4 v = __ldcs(&row[lane + i * 32]);   // evict-first stream
        float4 w = s_wenc[lane + i * 32];
        acc += v.x * w.x + v.y * w.y + v.z * w.z + v.w * w.w;
    }
#pragma unroll
    for (int o = 16; o > 0; o >>= 1)
        acc += __shfl_xor_sync(0xFFFFFFFFu, acc, o);

    if (lane == 0)
        out[(size_t)b * SRC_LEN + s] = acc;       // raw score

    // ---- blocks 0..31: g_edec[blockIdx] = dec . w_dec + bias (hidden) ----
    if (blockIdx.x < BATCH) {
        const int bb = blockIdx.x;
        const float4* dh = reinterpret_cast<const float4*>(dec_hidden + (size_t)bb * DIM);
        const float4* wd = reinterpret_cast<const float4*>(W);
        float4 a = dh[tid];
        float4 w = wd[tid];
        float ed = a.x * w.x + a.y * w.y + a.z * w.z + a.w * w.w;
#pragma unroll
        for (int o = 16; o > 0; o >>= 1)
            ed += __shfl_xor_sync(0xFFFFFFFFu, ed, o);
        if (lane == 0) red[warp] = ed;
        __syncthreads();
        if (tid == 0) {
            float t = 0.f;
#pragma unroll
            for (int i = 0; i < WARPS_PER_BLOCK; ++i) t += red[i];
            g_edec[bb] = t + bias[0];
        }
    }
}

// ---------------------------------------------------------------------------
// Kernel B (softmax): launched with programmatic dependent launch; parks at
// GridDependencySynchronize while kernel A streams, then does only real work:
// row load (L2-hot), tanh+exp, one shallow reduction, scale, store.
// tanh in [-1,1] -> exp cannot overflow -> no max pass.
// ---------------------------------------------------------------------------
#define SM_THREADS 512
#define SM_WARPS   (SM_THREADS / 32)        // 16
#define SM_VPT     (SRC_LEN / SM_THREADS)   // 4

__global__ void __launch_bounds__(SM_THREADS)
softmax_kernel(float* __restrict__ out)
{
    __shared__ float red[SM_WARPS];

#if __CUDA_ARCH__ >= 900
    cudaGridDependencySynchronize();        // wait for score grid completion
#endif

    const int b    = blockIdx.x;
    const int tid  = threadIdx.x;
    const int lane = tid & 31;
    const int warp = tid >> 5;

    float* row = out + (size_t)b * SRC_LEN;

    float v[SM_VPT];
#pragma unroll
    for (int i = 0; i < SM_VPT; ++i)
        v[i] = __ldcg(&row[tid + i * SM_THREADS]);   // L2-fresh

    const float edec_b = __ldcg(&g_edec[b]);

    float sum = 0.f;
#pragma unroll
    for (int i = 0; i < SM_VPT; ++i) {
        v[i] = __expf(tanhf(v[i] + edec_b));
        sum += v[i];
    }
#pragma unroll
    for (int o = 16; o > 0; o >>= 1)
        sum += __shfl_xor_sync(0xFFFFFFFFu, sum, o);
    if (lane == 0) red[warp] = sum;
    __syncthreads();
    if (warp == 0) {
        float t = (lane < SM_WARPS) ? red[lane] : 0.f;
#pragma unroll
        for (int o = 16; o > 0; o >>= 1)
            t += __shfl_xor_sync(0xFFFFFFFFu, t, o);
        if (lane == 0) red[0] = t;
    }
    __syncthreads();
    const float inv = 1.0f / red[0];

#pragma unroll
    for (int i = 0; i < SM_VPT; ++i)
        row[tid + i * SM_THREADS] = v[i] * inv;
}

// ---------------------------------------------------------------------------
extern "C" void kernel_launch(void* const* d_in, const int* in_sizes, int n_in,
                              void* d_out, int out_size)
{
    const float* dec_hidden  = (const float*)d_in[0];   // (32, 1024)
    const float* enc_outputs = (const float*)d_in[1];   // (2048, 32, 1024)
    const float* W           = (const float*)d_in[2];   // (1, 2048)
    const float* bias        = (const float*)d_in[3];   // (1,)
    float* out = (float*)d_out;                          // (32, 2048)

    score_kernel<<<TOTAL_ROWS / WARPS_PER_BLOCK, BLOCK_THREADS>>>(
        enc_outputs, W, dec_hidden, bias, out);

    // Softmax with programmatic dependent launch: overlaps its launch/dispatch
    // with the score kernel; data dependency enforced by GridDependencySync.
    cudaLaunchConfig_t cfg = {};
    cfg.gridDim  = dim3(BATCH, 1, 1);
    cfg.blockDim = dim3(SM_THREADS, 1, 1);
    cfg.dynamicSmemBytes = 0;
    cudaLaunchAttribute attrs[1];
    attrs[0].id = cudaLaunchAttributeProgrammaticStreamSerialization;
    attrs[0].val.programmaticStreamSerializationAllowed = 1;
    cfg.attrs = attrs;
    cfg.numAttrs = 1;
    cudaLaunchKernelEx(&cfg, softmax_kernel, out);
}